// round 1
// baseline (speedup 1.0000x reference)
#include <cuda_runtime.h>
#include <math.h>

#define NB 32
#define NC 256
#define NK 64
#define NHW 4096
#define NIN 320
#define BN_EPS 1e-5f

// ---------------- scratch (static device global; no allocation at runtime) ----
// layout offsets (floats)
#define OFF_CORR 0L                       // 32*64*4096
#define OFF_DW   8388608L                 // 32*320*4096
#define OFF_S    50331648L                // 32*256*4096
#define OFF_PX   83886080L                // 32*256*4096
#define OFF_G    117440512L               // 32*256*256
#define OFF_T1   119537664L
#define OFF_ATT  121634816L
#define OFF_T2   123731968L
#define OFF_M    125829120L
#define OFF_R    127926272L               // 32*256
#define OFF_U    127934464L
#define OFF_W    127942656L
#define OFF_CV   127950848L
#define SCRATCH_FLOATS 127959040L

__device__ float g_scratch[SCRATCH_FLOATS];

// =============================================================================
// Generic batched tiled GEMM: C[b] = A[b] * B[b]  (64x64 tile, 4x4/thread)
// AM: 0 = A row-major [M,K] (lda=Kd); 1 = A transposed, A[m,k] = Aptr[k*M+m]
// BM: 0 = B row-major [K,N] (ldb=N);  1 = B transposed, B[k,n] = Bptr[n*Kd+k]
// EPI: 0 none | 1 +bias(p0[m]) | 2 pw-bias+BN+ReLU (p0=b,p1=mean,p2=var,p3=g,p4=beta)
//      3 score epilogue (p0=u[b,m], p1=bk[n], p2=bq[m], p3=w[b,n]) * 1/16
//      4 final (+p0=cvec[b,m], +p1=s[b,m,n])
// =============================================================================
template<int AM, int BM, int EPI>
__global__ __launch_bounds__(256) void gemm_k(
    const float* __restrict__ A, const float* __restrict__ Bm, float* __restrict__ Cm,
    int M, int N, int Kd, long aBS, long bBS, long cBS,
    const float* __restrict__ p0, const float* __restrict__ p1,
    const float* __restrict__ p2, const float* __restrict__ p3,
    const float* __restrict__ p4)
{
    __shared__ float As[16][64];
    __shared__ float Bs[16][64];
    const int b = blockIdx.z;
    const float* Ab = A + (long)b * aBS;
    const float* Bb = Bm + (long)b * bBS;
    float* Cb = Cm + (long)b * cBS;
    const int n0 = blockIdx.x * 64;
    const int m0 = blockIdx.y * 64;
    const int t  = threadIdx.x;
    const int tx = t & 15, ty = t >> 4;

    float acc[4][4] = {};

    for (int k0 = 0; k0 < Kd; k0 += 16) {
        // ---- stage A tile ----
        if (AM == 0) {
            int m = t >> 2, kq = (t & 3) * 4;
            float4 va = *reinterpret_cast<const float4*>(&Ab[(long)(m0 + m) * Kd + k0 + kq]);
            As[kq + 0][m] = va.x; As[kq + 1][m] = va.y;
            As[kq + 2][m] = va.z; As[kq + 3][m] = va.w;
        } else {
            int kk = t >> 4, mq = (t & 15) * 4;
            float4 va = *reinterpret_cast<const float4*>(&Ab[(long)(k0 + kk) * M + m0 + mq]);
            *reinterpret_cast<float4*>(&As[kk][mq]) = va;
        }
        // ---- stage B tile ----
        if (BM == 0) {
            int kk = t >> 4, nq = (t & 15) * 4;
            float4 vb = *reinterpret_cast<const float4*>(&Bb[(long)(k0 + kk) * N + n0 + nq]);
            *reinterpret_cast<float4*>(&Bs[kk][nq]) = vb;
        } else {
            int n = t >> 2, kq = (t & 3) * 4;
            float4 vb = *reinterpret_cast<const float4*>(&Bb[(long)(n0 + n) * Kd + k0 + kq]);
            Bs[kq + 0][n] = vb.x; Bs[kq + 1][n] = vb.y;
            Bs[kq + 2][n] = vb.z; Bs[kq + 3][n] = vb.w;
        }
        __syncthreads();

        #pragma unroll
        for (int kk = 0; kk < 16; kk++) {
            float4 af = *reinterpret_cast<const float4*>(&As[kk][ty * 4]);
            float4 bf = *reinterpret_cast<const float4*>(&Bs[kk][tx * 4]);
            float a[4]  = {af.x, af.y, af.z, af.w};
            float bb[4] = {bf.x, bf.y, bf.z, bf.w};
            #pragma unroll
            for (int i = 0; i < 4; i++)
                #pragma unroll
                for (int j = 0; j < 4; j++)
                    acc[i][j] = fmaf(a[i], bb[j], acc[i][j]);
        }
        __syncthreads();
    }

    // ---- epilogue + store ----
    #pragma unroll
    for (int i = 0; i < 4; i++) {
        int m = m0 + ty * 4 + i;
        float vv[4];
        #pragma unroll
        for (int j = 0; j < 4; j++) {
            int n = n0 + tx * 4 + j;
            float x = acc[i][j];
            if (EPI == 1) {
                x += p0[m];
            } else if (EPI == 2) {
                x += p0[m];
                x = (x - p1[m]) * rsqrtf(p2[m] + BN_EPS);
                x = fmaf(x, p3[m], p4[m]);
                x = fmaxf(x, 0.0f);
            } else if (EPI == 3) {
                float u  = p0[b * NC + m];
                float bk = p1[n];
                float bq = p2[m];
                float w  = p3[b * NC + n];
                x = (x + u * bk + bq * w + 4096.0f * bq * bk) * 0.0625f;
            } else if (EPI == 4) {
                x += p0[b * NC + m] + p1[(long)b * cBS + (long)m * N + n];
            }
            vv[j] = x;
        }
        *reinterpret_cast<float4*>(&Cb[(long)m * N + n0 + tx * 4]) =
            make_float4(vv[0], vv[1], vv[2], vv[3]);
    }
}

// =============================================================================
// Depthwise 3x3 (pad 1) over concat([corr(64ch), d(256ch)]) -> g_dw
// one block per (b, channel); 64x64 plane staged in smem with halo
// =============================================================================
__global__ __launch_bounds__(256) void dw_k(
    const float* __restrict__ corr, const float* __restrict__ dten,
    const float* __restrict__ w, const float* __restrict__ bias,
    float* __restrict__ out)
{
    const int bc = blockIdx.x;
    const int b = bc / NIN, ch = bc % NIN;
    const float* src = (ch < NK) ? (corr + ((long)b * NK + ch) * NHW)
                                 : (dten + ((long)b * NC + (ch - NK)) * NHW);
    __shared__ float tile[66][66];
    const int t = threadIdx.x;
    for (int idx = t; idx < 66 * 66; idx += 256) {
        int yy = idx / 66, xx = idx % 66;
        int y = yy - 1, x = xx - 1;
        float v = 0.0f;
        if (y >= 0 && y < 64 && x >= 0 && x < 64) v = src[y * 64 + x];
        tile[yy][xx] = v;
    }
    __syncthreads();

    float wk[9];
    #pragma unroll
    for (int i = 0; i < 9; i++) wk[i] = w[ch * 9 + i];
    const float bb = bias[ch];

    float* dst = out + (long)bc * NHW;
    for (int idx = t; idx < NHW; idx += 256) {
        int y = idx >> 6, x = idx & 63;
        float acc = bb;
        #pragma unroll
        for (int ky = 0; ky < 3; ky++)
            #pragma unroll
            for (int kx = 0; kx < 3; kx++)
                acc = fmaf(wk[ky * 3 + kx], tile[y + ky][x + kx], acc);
        dst[idx] = acc;
    }
}

// =============================================================================
// row sums of px: r[b,c] = sum_n px[b,c,n]   (one warp per row)
// =============================================================================
__global__ __launch_bounds__(256) void rowsum_k(const float* __restrict__ px,
                                                float* __restrict__ r)
{
    int row = blockIdx.x * 8 + (threadIdx.x >> 5);
    int lane = threadIdx.x & 31;
    const float* p = px + (long)row * NHW;
    float s = 0.0f;
    for (int i = lane; i < NHW; i += 32) s += p[i];
    #pragma unroll
    for (int o = 16; o; o >>= 1) s += __shfl_xor_sync(0xffffffffu, s, o);
    if (lane == 0) r[row] = s;
}

// u = Wq r, w = Wk r  (per batch matvec)
__global__ __launch_bounds__(256) void uw_k(
    const float* __restrict__ Wq, const float* __restrict__ Wk,
    const float* __restrict__ r, float* __restrict__ u, float* __restrict__ w)
{
    int b = blockIdx.x, t = threadIdx.x;
    __shared__ float rs[NC];
    rs[t] = r[b * NC + t];
    __syncthreads();
    float uu = 0.0f, ww = 0.0f;
    for (int c = 0; c < NC; c++) {
        float rc = rs[c];
        uu = fmaf(Wq[t * NC + c], rc, uu);
        ww = fmaf(Wk[t * NC + c], rc, ww);
    }
    u[b * NC + t] = uu;
    w[b * NC + t] = ww;
}

// softmax over last dim of [B*C, C] rows, in place (256 threads = 1 row)
__global__ __launch_bounds__(256) void softmax_k(float* __restrict__ s)
{
    float* p = s + (long)blockIdx.x * NC;
    int t = threadIdx.x, lane = t & 31, wp = t >> 5;
    __shared__ float redm[8], reds[8];
    __shared__ float bm, bs;
    float v = p[t];
    float m = v;
    #pragma unroll
    for (int o = 16; o; o >>= 1) m = fmaxf(m, __shfl_xor_sync(0xffffffffu, m, o));
    if (lane == 0) redm[wp] = m;
    __syncthreads();
    if (t == 0) {
        float mm = redm[0];
        for (int i = 1; i < 8; i++) mm = fmaxf(mm, redm[i]);
        bm = mm;
    }
    __syncthreads();
    float e = expf(v - bm);
    float su = e;
    #pragma unroll
    for (int o = 16; o; o >>= 1) su += __shfl_xor_sync(0xffffffffu, su, o);
    if (lane == 0) reds[wp] = su;
    __syncthreads();
    if (t == 0) {
        float ss = 0.0f;
        for (int i = 0; i < 8; i++) ss += reds[i];
        bs = 1.0f / ss;
    }
    __syncthreads();
    p[t] = e * bs;
}

// y[d] = sum_c att[c,d]*bv[c];  cvec[o] = sum_d Wo[o,d]*y[d] + ob[o]
__global__ __launch_bounds__(256) void ycvec_k(
    const float* __restrict__ att, const float* __restrict__ bv,
    const float* __restrict__ Wo, const float* __restrict__ ob,
    float* __restrict__ cvec)
{
    int b = blockIdx.x, t = threadIdx.x;
    __shared__ float ys[NC];
    const float* ab = att + (long)b * NC * NC;
    float y = 0.0f;
    for (int c = 0; c < NC; c++) y = fmaf(ab[c * NC + t], bv[c], y);
    ys[t] = y;
    __syncthreads();
    float cv = 0.0f;
    for (int d = 0; d < NC; d++) cv = fmaf(Wo[t * NC + d], ys[d], cv);
    cvec[b * NC + t] = cv + ob[t];
}

// =============================================================================
extern "C" void kernel_launch(void* const* d_in, const int* in_sizes, int n_in,
                              void* d_out, int out_size)
{
    const float* z     = (const float*)d_in[0];
    const float* x     = (const float*)d_in[1];
    const float* dten  = (const float*)d_in[2];
    const float* dw_w  = (const float*)d_in[3];
    const float* dw_b  = (const float*)d_in[4];
    const float* pw_w  = (const float*)d_in[5];
    const float* pw_b  = (const float*)d_in[6];
    const float* bn_g  = (const float*)d_in[7];
    const float* bn_be = (const float*)d_in[8];
    const float* bn_m  = (const float*)d_in[9];
    const float* bn_v  = (const float*)d_in[10];
    const float* inp_w = (const float*)d_in[11];
    const float* inp_b = (const float*)d_in[12];
    const float* q_w   = (const float*)d_in[13];
    const float* q_b   = (const float*)d_in[14];
    const float* k_w   = (const float*)d_in[15];
    const float* k_b   = (const float*)d_in[16];
    const float* v_w   = (const float*)d_in[17];
    const float* v_b   = (const float*)d_in[18];
    const float* op_w  = (const float*)d_in[19];
    const float* op_b  = (const float*)d_in[20];
    float* out = (float*)d_out;

    float* base = nullptr;
    cudaGetSymbolAddress((void**)&base, g_scratch);
    float* corr = base + OFF_CORR;
    float* dwb  = base + OFF_DW;
    float* sbuf = base + OFF_S;
    float* px   = base + OFF_PX;
    float* G    = base + OFF_G;
    float* T1   = base + OFF_T1;
    float* att  = base + OFF_ATT;
    float* T2   = base + OFF_T2;
    float* Mm   = base + OFF_M;
    float* r    = base + OFF_R;
    float* u    = base + OFF_U;
    float* w    = base + OFF_W;
    float* cvec = base + OFF_CV;

    dim3 blk(256);
    const float* np = nullptr;

    // 1) correlation: corr[b] = z[b]^T (64x256) @ x[b] (256x4096)
    gemm_k<1,0,0><<<dim3(64,1,NB), blk>>>(z, x, corr, NK, NHW, NC,
        (long)NC*NK, (long)NC*NHW, (long)NK*NHW, np,np,np,np,np);

    // 2) depthwise 3x3 over concat(corr, d)
    dw_k<<<NB*NIN, blk>>>(corr, dten, dw_w, dw_b, dwb);

    // 3) pointwise + bias + BN + ReLU -> s
    gemm_k<0,0,2><<<dim3(64,4,NB), blk>>>(pw_w, dwb, sbuf, NC, NHW, NIN,
        0L, (long)NIN*NHW, (long)NC*NHW, pw_b, bn_m, bn_v, bn_g, bn_be);

    // 4) px = inp_w @ s + inp_b
    gemm_k<0,0,1><<<dim3(64,4,NB), blk>>>(inp_w, sbuf, px, NC, NHW, NC,
        0L, (long)NC*NHW, (long)NC*NHW, inp_b, np,np,np,np);

    // 5) r = px row sums
    rowsum_k<<<NB*NC/8, blk>>>(px, r);

    // 6) G[b] = px[b] @ px[b]^T  (256x256, K=4096)
    gemm_k<0,1,0><<<dim3(4,4,NB), blk>>>(px, px, G, NC, NC, NHW,
        (long)NC*NHW, (long)NC*NHW, (long)NC*NC, np,np,np,np,np);

    // 7) u = Wq r, w = Wk r
    uw_k<<<NB, blk>>>(q_w, k_w, r, u, w);

    // 8) T1 = Wq @ G
    gemm_k<0,0,0><<<dim3(4,4,NB), blk>>>(q_w, G, T1, NC, NC, NC,
        0L, (long)NC*NC, (long)NC*NC, np,np,np,np,np);

    // 9) score = (T1 @ Wk^T + u bk^T + bq w^T + N bq bk^T)/16
    gemm_k<0,1,3><<<dim3(4,4,NB), blk>>>(T1, k_w, att, NC, NC, NC,
        (long)NC*NC, 0L, (long)NC*NC, u, k_b, q_b, w, np);

    // 10) softmax rows
    softmax_k<<<NB*NC, blk>>>(att);

    // 11) cvec = Wo @ (att^T bv) + op_b
    ycvec_k<<<NB, blk>>>(att, v_b, op_w, op_b, cvec);

    // 12) T2 = att^T @ Wv
    gemm_k<1,0,0><<<dim3(4,4,NB), blk>>>(att, v_w, T2, NC, NC, NC,
        (long)NC*NC, 0L, (long)NC*NC, np,np,np,np,np);

    // 13) M = Wo @ T2
    gemm_k<0,0,0><<<dim3(4,4,NB), blk>>>(op_w, T2, Mm, NC, NC, NC,
        0L, (long)NC*NC, (long)NC*NC, np,np,np,np,np);

    // 14) out = M @ px + cvec + s
    gemm_k<0,0,4><<<dim3(64,4,NB), blk>>>(Mm, px, out, NC, NHW, NC,
        (long)NC*NC, (long)NC*NHW, (long)NC*NHW, cvec, sbuf, np,np,np);
}

// round 2
// speedup vs baseline: 1.0983x; 1.0983x over previous
#include <cuda_runtime.h>
#include <math.h>

#define NB 32
#define NC 256
#define NK 64
#define NHW 4096
#define NIN 320
#define BN_EPS 1e-5f

// ---------------- scratch (static device global; no allocation at runtime) ----
#define OFF_CORR 0L                       // 32*64*4096
#define OFF_DW   8388608L                 // 32*320*4096
#define OFF_S    50331648L                // 32*256*4096
#define OFF_PX   83886080L                // 32*256*4096
#define OFF_G    117440512L               // 32*256*256
#define OFF_T1   119537664L
#define OFF_ATT  121634816L
#define OFF_T2   123731968L
#define OFF_M    125829120L
#define OFF_R    127926272L               // 32*256
#define OFF_U    127934464L
#define OFF_W    127942656L
#define OFF_CV   127950848L
#define SCRATCH_FLOATS 127959040L

__device__ float g_scratch[SCRATCH_FLOATS];

// =============================================================================
// Big GEMM: 128x128 block tile, BK=8, 8x8 per thread, 256 threads.
// A always row-major [M,K]. BMODE: 0 = B row-major [K,N]; 1 = B is [N,K] (B^T).
// EPI: 0 none | 1 +bias(p0[m]) | 2 bias+BN+ReLU | 4 final (+cvec +s)
// SPLIT: K-split factor; if >1 epilogue is atomicAdd (C must be zeroed first).
// =============================================================================
template<int BMODE, int EPI, int SPLIT>
__global__ __launch_bounds__(256) void gemm128_k(
    const float* __restrict__ A, const float* __restrict__ Bm, float* __restrict__ Cm,
    int M, int N, int Kd, long aBS, long bBS, long cBS,
    const float* __restrict__ p0, const float* __restrict__ p1,
    const float* __restrict__ p2, const float* __restrict__ p3,
    const float* __restrict__ p4)
{
    __shared__ float As[8][132];
    __shared__ float Bs[8][132];
    const int b  = blockIdx.z / SPLIT;
    const int ks = blockIdx.z % SPLIT;
    const int KC = Kd / SPLIT;
    const float* Ab = A  + (long)b * aBS;
    const float* Bb = Bm + (long)b * bBS;
    float* Cb = Cm + (long)b * cBS;
    const int n0 = blockIdx.x * 128;
    const int m0 = blockIdx.y * 128;
    const int t  = threadIdx.x;
    const int tx = t & 15, ty = t >> 4;

    float acc[8][8] = {};

    const int arow = t >> 1, akq = (t & 1) * 4;
    const int kend = (ks + 1) * KC;
    for (int k0 = ks * KC; k0 < kend; k0 += 8) {
        // ---- stage A tile: As[kk][m] ----
        {
            float4 va = *reinterpret_cast<const float4*>(&Ab[(long)(m0 + arow) * Kd + k0 + akq]);
            As[akq + 0][arow] = va.x; As[akq + 1][arow] = va.y;
            As[akq + 2][arow] = va.z; As[akq + 3][arow] = va.w;
        }
        // ---- stage B tile: Bs[kk][n] ----
        if (BMODE == 0) {
            int kk = t >> 5, nq = (t & 31) * 4;
            float4 vb = *reinterpret_cast<const float4*>(&Bb[(long)(k0 + kk) * N + n0 + nq]);
            *reinterpret_cast<float4*>(&Bs[kk][nq]) = vb;
        } else {
            int n = t >> 1, kq = (t & 1) * 4;
            float4 vb = *reinterpret_cast<const float4*>(&Bb[(long)(n0 + n) * Kd + k0 + kq]);
            Bs[kq + 0][n] = vb.x; Bs[kq + 1][n] = vb.y;
            Bs[kq + 2][n] = vb.z; Bs[kq + 3][n] = vb.w;
        }
        __syncthreads();

        #pragma unroll
        for (int kk = 0; kk < 8; kk++) {
            float4 a0 = *reinterpret_cast<const float4*>(&As[kk][ty * 8]);
            float4 a1 = *reinterpret_cast<const float4*>(&As[kk][ty * 8 + 4]);
            float4 b0 = *reinterpret_cast<const float4*>(&Bs[kk][tx * 8]);
            float4 b1 = *reinterpret_cast<const float4*>(&Bs[kk][tx * 8 + 4]);
            float a[8]  = {a0.x, a0.y, a0.z, a0.w, a1.x, a1.y, a1.z, a1.w};
            float bb[8] = {b0.x, b0.y, b0.z, b0.w, b1.x, b1.y, b1.z, b1.w};
            #pragma unroll
            for (int i = 0; i < 8; i++)
                #pragma unroll
                for (int j = 0; j < 8; j++)
                    acc[i][j] = fmaf(a[i], bb[j], acc[i][j]);
        }
        __syncthreads();
    }

    // ---- epilogue ----
    #pragma unroll
    for (int i = 0; i < 8; i++) {
        int m = m0 + ty * 8 + i;
        if (SPLIT > 1) {
            #pragma unroll
            for (int j = 0; j < 8; j++) {
                int n = n0 + tx * 8 + j;
                atomicAdd(&Cb[(long)m * N + n], acc[i][j]);
            }
        } else {
            float bias = 0.0f, scale = 1.0f, beta = 0.0f;
            if (EPI == 1) bias = p0[m];
            if (EPI == 2) {
                bias = p0[m];
                scale = rsqrtf(p2[m] + BN_EPS) * p3[m];
                beta = p4[m] - (p1[m] - p0[m]) * 0.0f; // placeholder, computed below
            }
            float cv = 0.0f;
            if (EPI == 4) cv = p0[b * NC + m];
            float vv[8];
            #pragma unroll
            for (int j = 0; j < 8; j++) {
                int n = n0 + tx * 8 + j;
                float x = acc[i][j];
                if (EPI == 1) {
                    x += bias;
                } else if (EPI == 2) {
                    x += bias;
                    x = (x - p1[m]) * scale + p4[m];
                    x = fmaxf(x, 0.0f);
                } else if (EPI == 4) {
                    x += cv + p1[(long)b * cBS + (long)m * N + n];
                }
                vv[j] = x;
            }
            *reinterpret_cast<float4*>(&Cb[(long)m * N + n0 + tx * 8]) =
                make_float4(vv[0], vv[1], vv[2], vv[3]);
            *reinterpret_cast<float4*>(&Cb[(long)m * N + n0 + tx * 8 + 4]) =
                make_float4(vv[4], vv[5], vv[6], vv[7]);
        }
    }
}

__global__ void zero_k(float* __restrict__ p, long n)
{
    long i = (long)blockIdx.x * blockDim.x + threadIdx.x;
    if (i < n) p[i] = 0.0f;
}

// =============================================================================
// Small GEMM: 64x64 tile, 4x4/thread (used for corr M=64 and 256^3 GEMMs)
// AM: 0 = A row-major [M,K]; 1 = A^T (A[m,k] = Aptr[k*M+m])
// BM: 0 = B row-major [K,N]; 1 = B^T (B[k,n] = Bptr[n*K+k])
// EPI: 0 none | 3 score epilogue
// =============================================================================
template<int AM, int BM, int EPI>
__global__ __launch_bounds__(256) void gemm_k(
    const float* __restrict__ A, const float* __restrict__ Bm, float* __restrict__ Cm,
    int M, int N, int Kd, long aBS, long bBS, long cBS,
    const float* __restrict__ p0, const float* __restrict__ p1,
    const float* __restrict__ p2, const float* __restrict__ p3)
{
    __shared__ float As[16][64];
    __shared__ float Bs[16][64];
    const int b = blockIdx.z;
    const float* Ab = A + (long)b * aBS;
    const float* Bb = Bm + (long)b * bBS;
    float* Cb = Cm + (long)b * cBS;
    const int n0 = blockIdx.x * 64;
    const int m0 = blockIdx.y * 64;
    const int t  = threadIdx.x;
    const int tx = t & 15, ty = t >> 4;

    float acc[4][4] = {};

    for (int k0 = 0; k0 < Kd; k0 += 16) {
        if (AM == 0) {
            int m = t >> 2, kq = (t & 3) * 4;
            float4 va = *reinterpret_cast<const float4*>(&Ab[(long)(m0 + m) * Kd + k0 + kq]);
            As[kq + 0][m] = va.x; As[kq + 1][m] = va.y;
            As[kq + 2][m] = va.z; As[kq + 3][m] = va.w;
        } else {
            int kk = t >> 4, mq = (t & 15) * 4;
            float4 va = *reinterpret_cast<const float4*>(&Ab[(long)(k0 + kk) * M + m0 + mq]);
            *reinterpret_cast<float4*>(&As[kk][mq]) = va;
        }
        if (BM == 0) {
            int kk = t >> 4, nq = (t & 15) * 4;
            float4 vb = *reinterpret_cast<const float4*>(&Bb[(long)(k0 + kk) * N + n0 + nq]);
            *reinterpret_cast<float4*>(&Bs[kk][nq]) = vb;
        } else {
            int n = t >> 2, kq = (t & 3) * 4;
            float4 vb = *reinterpret_cast<const float4*>(&Bb[(long)(n0 + n) * Kd + k0 + kq]);
            Bs[kq + 0][n] = vb.x; Bs[kq + 1][n] = vb.y;
            Bs[kq + 2][n] = vb.z; Bs[kq + 3][n] = vb.w;
        }
        __syncthreads();

        #pragma unroll
        for (int kk = 0; kk < 16; kk++) {
            float4 af = *reinterpret_cast<const float4*>(&As[kk][ty * 4]);
            float4 bf = *reinterpret_cast<const float4*>(&Bs[kk][tx * 4]);
            float a[4]  = {af.x, af.y, af.z, af.w};
            float bb[4] = {bf.x, bf.y, bf.z, bf.w};
            #pragma unroll
            for (int i = 0; i < 4; i++)
                #pragma unroll
                for (int j = 0; j < 4; j++)
                    acc[i][j] = fmaf(a[i], bb[j], acc[i][j]);
        }
        __syncthreads();
    }

    #pragma unroll
    for (int i = 0; i < 4; i++) {
        int m = m0 + ty * 4 + i;
        float vv[4];
        #pragma unroll
        for (int j = 0; j < 4; j++) {
            int n = n0 + tx * 4 + j;
            float x = acc[i][j];
            if (EPI == 3) {
                float u  = p0[b * NC + m];
                float bk = p1[n];
                float bq = p2[m];
                float w  = p3[b * NC + n];
                x = (x + u * bk + bq * w + 4096.0f * bq * bk) * 0.0625f;
            }
            vv[j] = x;
        }
        *reinterpret_cast<float4*>(&Cb[(long)m * N + n0 + tx * 4]) =
            make_float4(vv[0], vv[1], vv[2], vv[3]);
    }
}

// =============================================================================
// Depthwise 3x3 (pad 1) over concat([corr(64ch), d(256ch)])
// =============================================================================
__global__ __launch_bounds__(256) void dw_k(
    const float* __restrict__ corr, const float* __restrict__ dten,
    const float* __restrict__ w, const float* __restrict__ bias,
    float* __restrict__ out)
{
    const int bc = blockIdx.x;
    const int b = bc / NIN, ch = bc % NIN;
    const float* src = (ch < NK) ? (corr + ((long)b * NK + ch) * NHW)
                                 : (dten + ((long)b * NC + (ch - NK)) * NHW);
    __shared__ float tile[66][66];
    const int t = threadIdx.x;
    for (int idx = t; idx < 66 * 66; idx += 256) {
        int yy = idx / 66, xx = idx % 66;
        int y = yy - 1, x = xx - 1;
        float v = 0.0f;
        if (y >= 0 && y < 64 && x >= 0 && x < 64) v = src[y * 64 + x];
        tile[yy][xx] = v;
    }
    __syncthreads();

    float wk[9];
    #pragma unroll
    for (int i = 0; i < 9; i++) wk[i] = w[ch * 9 + i];
    const float bb = bias[ch];

    float* dst = out + (long)bc * NHW;
    for (int idx = t; idx < NHW; idx += 256) {
        int y = idx >> 6, x = idx & 63;
        float acc = bb;
        #pragma unroll
        for (int ky = 0; ky < 3; ky++)
            #pragma unroll
            for (int kx = 0; kx < 3; kx++)
                acc = fmaf(wk[ky * 3 + kx], tile[y + ky][x + kx], acc);
        dst[idx] = acc;
    }
}

// row sums of px
__global__ __launch_bounds__(256) void rowsum_k(const float* __restrict__ px,
                                                float* __restrict__ r)
{
    int row = blockIdx.x * 8 + (threadIdx.x >> 5);
    int lane = threadIdx.x & 31;
    const float* p = px + (long)row * NHW;
    float s = 0.0f;
    for (int i = lane; i < NHW; i += 32) s += p[i];
    #pragma unroll
    for (int o = 16; o; o >>= 1) s += __shfl_xor_sync(0xffffffffu, s, o);
    if (lane == 0) r[row] = s;
}

// u = Wq r, w = Wk r
__global__ __launch_bounds__(256) void uw_k(
    const float* __restrict__ Wq, const float* __restrict__ Wk,
    const float* __restrict__ r, float* __restrict__ u, float* __restrict__ w)
{
    int b = blockIdx.x, t = threadIdx.x;
    __shared__ float rs[NC];
    rs[t] = r[b * NC + t];
    __syncthreads();
    float uu = 0.0f, ww = 0.0f;
    for (int c = 0; c < NC; c++) {
        float rc = rs[c];
        uu = fmaf(Wq[t * NC + c], rc, uu);
        ww = fmaf(Wk[t * NC + c], rc, ww);
    }
    u[b * NC + t] = uu;
    w[b * NC + t] = ww;
}

// softmax over rows of [B*C, C], in place
__global__ __launch_bounds__(256) void softmax_k(float* __restrict__ s)
{
    float* p = s + (long)blockIdx.x * NC;
    int t = threadIdx.x, lane = t & 31, wp = t >> 5;
    __shared__ float redm[8], reds[8];
    __shared__ float bm, bs;
    float v = p[t];
    float m = v;
    #pragma unroll
    for (int o = 16; o; o >>= 1) m = fmaxf(m, __shfl_xor_sync(0xffffffffu, m, o));
    if (lane == 0) redm[wp] = m;
    __syncthreads();
    if (t == 0) {
        float mm = redm[0];
        for (int i = 1; i < 8; i++) mm = fmaxf(mm, redm[i]);
        bm = mm;
    }
    __syncthreads();
    float e = expf(v - bm);
    float su = e;
    #pragma unroll
    for (int o = 16; o; o >>= 1) su += __shfl_xor_sync(0xffffffffu, su, o);
    if (lane == 0) reds[wp] = su;
    __syncthreads();
    if (t == 0) {
        float ss = 0.0f;
        for (int i = 0; i < 8; i++) ss += reds[i];
        bs = 1.0f / ss;
    }
    __syncthreads();
    p[t] = e * bs;
}

// cvec = Wo @ (att^T bv) + op_b
__global__ __launch_bounds__(256) void ycvec_k(
    const float* __restrict__ att, const float* __restrict__ bv,
    const float* __restrict__ Wo, const float* __restrict__ ob,
    float* __restrict__ cvec)
{
    int b = blockIdx.x, t = threadIdx.x;
    __shared__ float ys[NC];
    const float* ab = att + (long)b * NC * NC;
    float y = 0.0f;
    for (int c = 0; c < NC; c++) y = fmaf(ab[c * NC + t], bv[c], y);
    ys[t] = y;
    __syncthreads();
    float cv = 0.0f;
    for (int d = 0; d < NC; d++) cv = fmaf(Wo[t * NC + d], ys[d], cv);
    cvec[b * NC + t] = cv + ob[t];
}

// =============================================================================
extern "C" void kernel_launch(void* const* d_in, const int* in_sizes, int n_in,
                              void* d_out, int out_size)
{
    const float* z     = (const float*)d_in[0];
    const float* x     = (const float*)d_in[1];
    const float* dten  = (const float*)d_in[2];
    const float* dw_w  = (const float*)d_in[3];
    const float* dw_b  = (const float*)d_in[4];
    const float* pw_w  = (const float*)d_in[5];
    const float* pw_b  = (const float*)d_in[6];
    const float* bn_g  = (const float*)d_in[7];
    const float* bn_be = (const float*)d_in[8];
    const float* bn_m  = (const float*)d_in[9];
    const float* bn_v  = (const float*)d_in[10];
    const float* inp_w = (const float*)d_in[11];
    const float* inp_b = (const float*)d_in[12];
    const float* q_w   = (const float*)d_in[13];
    const float* q_b   = (const float*)d_in[14];
    const float* k_w   = (const float*)d_in[15];
    const float* k_b   = (const float*)d_in[16];
    const float* v_w   = (const float*)d_in[17];
    const float* v_b   = (const float*)d_in[18];
    const float* op_w  = (const float*)d_in[19];
    const float* op_b  = (const float*)d_in[20];
    float* out = (float*)d_out;

    float* base = nullptr;
    cudaGetSymbolAddress((void**)&base, g_scratch);
    float* corr = base + OFF_CORR;
    float* dwb  = base + OFF_DW;
    float* sbuf = base + OFF_S;
    float* px   = base + OFF_PX;
    float* G    = base + OFF_G;
    float* T1   = base + OFF_T1;
    float* att  = base + OFF_ATT;
    float* T2   = base + OFF_T2;
    float* Mm   = base + OFF_M;
    float* r    = base + OFF_R;
    float* u    = base + OFF_U;
    float* w    = base + OFF_W;
    float* cvec = base + OFF_CV;

    dim3 blk(256);
    const float* np = nullptr;

    // 1) correlation: corr[b] = z[b]^T (64x256) @ x[b] (256x4096)
    gemm_k<1,0,0><<<dim3(64,1,NB), blk>>>(z, x, corr, NK, NHW, NC,
        (long)NC*NK, (long)NC*NHW, (long)NK*NHW, np,np,np,np);

    // 2) depthwise 3x3 over concat(corr, d)
    dw_k<<<NB*NIN, blk>>>(corr, dten, dw_w, dw_b, dwb);

    // 3) pointwise + bias + BN + ReLU -> s
    gemm128_k<0,2,1><<<dim3(32,2,NB), blk>>>(pw_w, dwb, sbuf, NC, NHW, NIN,
        0L, (long)NIN*NHW, (long)NC*NHW, pw_b, bn_m, bn_v, bn_g, bn_be);

    // 4) px = inp_w @ s + inp_b
    gemm128_k<0,1,1><<<dim3(32,2,NB), blk>>>(inp_w, sbuf, px, NC, NHW, NC,
        0L, (long)NC*NHW, (long)NC*NHW, inp_b, np,np,np,np);

    // 5) r = px row sums
    rowsum_k<<<NB*NC/8, blk>>>(px, r);

    // 6) G[b] = px[b] @ px[b]^T  (split-K x8 with atomicAdd)
    zero_k<<<(NB*NC*NC + 1023)/1024, 1024>>>(G, (long)NB*NC*NC);
    gemm128_k<1,0,8><<<dim3(2,2,NB*8), blk>>>(px, px, G, NC, NC, NHW,
        (long)NC*NHW, (long)NC*NHW, (long)NC*NC, np,np,np,np,np);

    // 7) u = Wq r, w = Wk r
    uw_k<<<NB, blk>>>(q_w, k_w, r, u, w);

    // 8) T1 = Wq @ G
    gemm_k<0,0,0><<<dim3(4,4,NB), blk>>>(q_w, G, T1, NC, NC, NC,
        0L, (long)NC*NC, (long)NC*NC, np,np,np,np);

    // 9) score = (T1 @ Wk^T + u bk^T + bq w^T + N bq bk^T)/16
    gemm_k<0,1,3><<<dim3(4,4,NB), blk>>>(T1, k_w, att, NC, NC, NC,
        (long)NC*NC, 0L, (long)NC*NC, u, k_b, q_b, w);

    // 10) softmax rows
    softmax_k<<<NB*NC, blk>>>(att);

    // 11) cvec = Wo @ (att^T bv) + op_b
    ycvec_k<<<NB, blk>>>(att, v_b, op_w, op_b, cvec);

    // 12) T2 = att^T @ Wv
    gemm_k<1,0,0><<<dim3(4,4,NB), blk>>>(att, v_w, T2, NC, NC, NC,
        (long)NC*NC, 0L, (long)NC*NC, np,np,np,np);

    // 13) M = Wo @ T2
    gemm_k<0,0,0><<<dim3(4,4,NB), blk>>>(op_w, T2, Mm, NC, NC, NC,
        0L, (long)NC*NC, (long)NC*NC, np,np,np,np);

    // 14) out = M @ px + cvec + s
    gemm128_k<0,4,1><<<dim3(32,2,NB), blk>>>(Mm, px, out, NC, NHW, NC,
        (long)NC*NC, (long)NC*NHW, (long)NC*NHW, cvec, sbuf, np,np,np);
}